// round 13
// baseline (speedup 1.0000x reference)
#include <cuda_runtime.h>
#include <cstdint>

#define NSTEP 2176
#define BURN  128
#define DIMX  512
#define HID   1024
#define GT    16            // t-tile for dz GEMM

// ---------------- scratch (device globals: no allocation allowed) ----------
__device__ float g_dx[NSTEP * DIMX];   // scaled noise: normal * 0.1
__device__ float g_u [NSTEP];          // per-step uniforms
__device__ float g_dz[NSTEP * HID];    // dz[t][j] = sum_i dx[t][i] * W1[i][j]
__device__ float g_z0[HID];            // z0 = x0 @ W1 + b1

// ---------------- threefry2x32 (JAX-exact, partitionable) ------------------
__device__ __forceinline__ uint32_t rotl32(uint32_t v, int r) {
    return (v << r) | (v >> (32 - r));
}
__device__ __forceinline__ void tf2x32(uint32_t k0, uint32_t k1,
                                       uint32_t x0, uint32_t x1,
                                       uint32_t& o0, uint32_t& o1) {
    uint32_t k2 = k0 ^ k1 ^ 0x1BD11BDAu;
    x0 += k0; x1 += k1;
#define TF_R(R) { x0 += x1; x1 = rotl32(x1, R); x1 ^= x0; }
    TF_R(13) TF_R(15) TF_R(26) TF_R(6)
    x0 += k1; x1 += k2 + 1u;
    TF_R(17) TF_R(29) TF_R(16) TF_R(24)
    x0 += k2; x1 += k0 + 2u;
    TF_R(13) TF_R(15) TF_R(26) TF_R(6)
    x0 += k0; x1 += k1 + 3u;
    TF_R(17) TF_R(29) TF_R(16) TF_R(24)
    x0 += k1; x1 += k2 + 4u;
    TF_R(13) TF_R(15) TF_R(26) TF_R(6)
    x0 += k2; x1 += k0 + 5u;
#undef TF_R
    o0 = x0; o1 = x1;
}

__device__ __forceinline__ uint32_t rbits32(uint32_t k0, uint32_t k1, uint32_t idx) {
    uint32_t o0, o1;
    tf2x32(k0, k1, 0u, idx, o0, o1);
    return o0 ^ o1;
}

__device__ __forceinline__ float bits_to_unit(uint32_t b) {
    return __uint_as_float((b >> 9) | 0x3f800000u) - 1.0f;
}

// XLA ErfInv32 (Giles). log1pf == libdevice __nv_log1pf == what XLA emits.
__device__ __forceinline__ float erfinv_xla(float x) {
    float xx = x * x;
    float w = -log1pf(-xx);
    float p;
    if (w < 5.0f) {
        w = w - 2.5f;
        p = 2.81022636e-08f;
        p = fmaf(p, w, 3.43273939e-07f);
        p = fmaf(p, w, -3.5233877e-06f);
        p = fmaf(p, w, -4.39150654e-06f);
        p = fmaf(p, w, 0.00021858087f);
        p = fmaf(p, w, -0.00125372503f);
        p = fmaf(p, w, -0.00417768164f);
        p = fmaf(p, w, 0.246640727f);
        p = fmaf(p, w, 1.50140941f);
    } else {
        w = __fsqrt_rn(w) - 3.0f;
        p = -0.000200214257f;
        p = fmaf(p, w, 0.000100950558f);
        p = fmaf(p, w, 0.00134934322f);
        p = fmaf(p, w, -0.00367342844f);
        p = fmaf(p, w, 0.00573950773f);
        p = fmaf(p, w, -0.0076224613f);
        p = fmaf(p, w, 0.00943887047f);
        p = fmaf(p, w, 1.00167406f);
        p = fmaf(p, w, 2.83297682f);
    }
    return p * x;
}

// ---------------- f32x2 packed helpers (Blackwell) --------------------------
typedef unsigned long long ull;
__device__ __forceinline__ ull pk2(float a, float b) {
    ull r; asm("mov.b64 %0, {%1, %2};" : "=l"(r) : "f"(a), "f"(b)); return r;
}
__device__ __forceinline__ void upk2(float& a, float& b, ull v) {
    asm("mov.b64 {%0, %1}, %2;" : "=f"(a), "=f"(b) : "l"(v));
}
__device__ __forceinline__ ull cst2(float c) {
    uint32_t u = __float_as_uint(c);
    return ((ull)u << 32) | (ull)u;
}
#define FMA2(d, a, b, c) asm("fma.rn.f32x2 %0, %1, %2, %3;" : "=l"(d) : "l"(a), "l"(b), "l"(c))
#define MUL2(d, a, b)    asm("mul.rn.f32x2 %0, %1, %2;"     : "=l"(d) : "l"(a), "l"(b))
#define ADD2(d, a, b)    asm("add.rn.f32x2 %0, %1, %2;"     : "=l"(d) : "l"(a), "l"(b))
// d = a - b  (one FMA2: a + (-1)*b)
#define SUB2(d, a, b)    asm("fma.rn.f32x2 %0, %1, %2, %3;" : "=l"(d) : "l"(b), "l"(0xBF800000BF800000ULL), "l"(a))

__device__ __forceinline__ float rcp_approx(float x) {
    float r; asm("rcp.approx.f32 %0, %1;" : "=f"(r) : "f"(x)); return r;
}
__device__ __forceinline__ float ex2_approx(float x) {
    float r; asm("ex2.approx.f32 %0, %1;" : "=f"(r) : "f"(x)); return r;
}

// MUFU-pipe tanh over a packed pair: tanh(x) = 1 - 2/(e^{2x}+1)
__device__ __forceinline__ void tanh2_mufu(ull X, float& ra, float& rb) {
    ull S; MUL2(S, X, cst2(2.8853900817779268f));   // 2*log2(e)*x
    float sa, sb; upk2(sa, sb, S);
    float Ea = ex2_approx(sa), Eb = ex2_approx(sb); // e^{2x}
    ull D; ADD2(D, pk2(Ea, Eb), cst2(1.0f));
    float da, db; upk2(da, db, D);
    ull R = pk2(rcp_approx(da), rcp_approx(db));
    ull T; FMA2(T, R, cst2(-2.0f), cst2(1.0f));
    upk2(ra, rb, T);
}

// ---------------- kernel 1: precompute all noise / uniforms ----------------
__global__ void __launch_bounds__(256) noise_kernel() {
    const int t = blockIdx.x;
    const int tid = threadIdx.x;

    uint32_t kt0, kt1;
    tf2x32(0u, 1u, 0u, (uint32_t)t, kt0, kt1);

    uint32_t n0, n1, u0, u1;
    tf2x32(kt0, kt1, 0u, 0u, n0, n1);   // k_noise
    tf2x32(kt0, kt1, 0u, 1u, u0, u1);   // k_unif

    const float LO = __uint_as_float(0xBF7FFFFFu);      // nextafter(-1,0)
    const float SQRT2 = __uint_as_float(0x3FB504F3u);   // f32(sqrt(2))
    const float STEP = 0.1f;

#pragma unroll
    for (int h = 0; h < 2; ++h) {
        int i = tid + h * 256;
        uint32_t b = rbits32(n0, n1, (uint32_t)i);
        float f = bits_to_unit(b);
        float u = fmaxf(LO, f * 2.0f + LO);
        float nv = SQRT2 * erfinv_xla(u);
        g_dx[t * DIMX + i] = nv * STEP;
    }

    if (tid == 0) {
        uint32_t b = rbits32(u0, u1, 0u);
        g_u[t] = bits_to_unit(b);
    }
}

// ---------------- kernel 2: dz[t][j] = dx[t] @ W1 (packed t-pairs) ---------
__global__ void __launch_bounds__(256) dz_gemm(const float* __restrict__ W1) {
    __shared__ float dxs[GT * DIMX];            // 32 KB
    const int tx = threadIdx.x;
    const int j  = blockIdx.x * 256 + tx;
    const int t0 = blockIdx.y * GT;

    for (int k = tx; k < GT * DIMX; k += 256) dxs[k] = g_dx[t0 * DIMX + k];
    __syncthreads();

    ull acc[GT / 2];
#pragma unroll
    for (int q = 0; q < GT / 2; ++q) acc[q] = 0;

#pragma unroll 4
    for (int i = 0; i < DIMX; ++i) {
        float wv = W1[i * HID + j];
        ull WV = pk2(wv, wv);
#pragma unroll
        for (int q = 0; q < GT / 2; ++q) {
            ull DX = pk2(dxs[(2 * q) * DIMX + i], dxs[(2 * q + 1) * DIMX + i]);
            FMA2(acc[q], WV, DX, acc[q]);
        }
    }
#pragma unroll
    for (int q = 0; q < GT / 2; ++q) {
        float a, b; upk2(a, b, acc[q]);
        g_dz[(t0 + 2 * q) * HID + j] = a;
        g_dz[(t0 + 2 * q + 1) * HID + j] = b;
    }
}

// ---------------- kernel 3: z0 = x0 @ W1 + b1 ------------------------------
__global__ void __launch_bounds__(256) z0_kernel(const float* __restrict__ x0,
                                                 const float* __restrict__ W1,
                                                 const float* __restrict__ b1) {
    __shared__ float xs[DIMX];
    const int tx = threadIdx.x;
    const int j  = blockIdx.x * 256 + tx;
    for (int k = tx; k < DIMX; k += 256) xs[k] = x0[k];
    __syncthreads();
    float acc = 0.0f;
    for (int i = 0; i < DIMX; ++i)
        acc = fmaf(xs[i], W1[i * HID + j], acc);
    g_z0[j] = acc + b1[j];
}

// ---------------- kernel 4: chain, ONE CTA, 512 thr, SINGLE-STEP loop ------
// Thread owns hidden cols (tid, tid+512) packed as one f32x2, and x dim tid.
__global__ void __launch_bounds__(512, 1) chain_kernel(
    const float* __restrict__ x0, const float* __restrict__ W2,
    const float* __restrict__ b2, float* __restrict__ out)
{
    __shared__ float red[2][16];        // [parity][warp]
    __shared__ float us[NSTEP];

    const int tid  = threadIdx.x;
    const int lane = tid & 31;
    const int wid  = tid >> 5;          // 16 warps

    for (int k = tid; k < NSTEP; k += 512) us[k] = g_u[k];

    ull zP = pk2(g_z0[tid], g_z0[tid + DIMX]);   // b1 folded in
    ull cP = 0;                                   // Kahan compensation (0.0,0.0)
    const float W2a = W2[tid], W2b = W2[tid + DIMX];
    const float b2v = b2[0];
    float xr = x0[tid];
    float p_old;

    // ---- initial p_old = psi2(x0) (parity 1 slot) ----
    {
        float ta, tb; tanh2_mufu(zP, ta, tb);
        float y = fmaf(tb, W2b, ta * W2a);
#pragma unroll
        for (int off = 16; off; off >>= 1)
            y += __shfl_xor_sync(0xffffffffu, y, off);
        if (lane == 0) red[1][wid] = y;
        __syncthreads();
        float s = red[1][lane & 15];
#pragma unroll
        for (int off = 8; off; off >>= 1)
            s += __shfl_xor_sync(0xffffffffu, s, off);
        float m = s + b2v;
        p_old = m * m;
        __syncthreads();
    }

    // prefetch step 0
    ull d = pk2(g_dz[0 * HID + tid], g_dz[0 * HID + tid + DIMX]);
    float dx = g_dx[0 * DIMX + tid];

    for (int t = 0; t < NSTEP; ++t) {
        const int par = t & 1;

        // candidate (packed bitwise replay of the sequential Kahan recurrence)
        ull e;  SUB2(e, d, cP);
        ull v;  ADD2(v, zP, e);
        ull tt; SUB2(tt, v, zP);
        ull c0; SUB2(c0, tt, e);

        float ta, tb; tanh2_mufu(v, ta, tb);
        float y = fmaf(tb, W2b, ta * W2a);

        // stage 1: intra-warp butterfly
#pragma unroll
        for (int off = 16; off; off >>= 1)
            y += __shfl_xor_sync(0xffffffffu, y, off);
        if (lane == 0) red[par][wid] = y;
        __syncthreads();

        // prefetch next step (overlaps stage 2)
        ull nd = 0;
        float ndx = 0.f;
        if (t + 1 < NSTEP) {
            nd = pk2(g_dz[(t + 1) * HID + tid], g_dz[(t + 1) * HID + tid + DIMX]);
            ndx = g_dx[(t + 1) * DIMX + tid];
        }

        // stage 2: every warp redundantly reduces the 16 partials
        float s = red[par][lane & 15];
#pragma unroll
        for (int off = 8; off; off >>= 1)
            s += __shfl_xor_sync(0xffffffffu, s, off);

        // decision (uniform): u < min(p_new/(p_old+eps),1) <=> u*(p_old+eps) < p_new
        float mm = s + b2v;
        float p_new = mm * mm;
        bool acc = us[t] * (p_old + 1e-12f) < p_new;
        if (acc) { zP = v; cP = c0; p_old = p_new; xr += dx; }
        if (t >= BURN) out[(t - BURN) * DIMX + tid] = xr;

        d = nd; dx = ndx;
    }
}

// ---------------- launch ----------------------------------------------------
extern "C" void kernel_launch(void* const* d_in, const int* in_sizes, int n_in,
                              void* d_out, int out_size) {
    const float* x0 = (const float*)d_in[0];
    const float* W1 = (const float*)d_in[1];
    const float* b1 = (const float*)d_in[2];
    const float* W2 = (const float*)d_in[3];
    const float* b2 = (const float*)d_in[4];
    float* out = (float*)d_out;

    noise_kernel<<<NSTEP, 256>>>();
    dz_gemm<<<dim3(HID / 256, NSTEP / GT), 256>>>(W1);
    z0_kernel<<<HID / 256, 256>>>(x0, W1, b1);
    chain_kernel<<<1, 512>>>(x0, W2, b2, out);
}

// round 14
// speedup vs baseline: 1.2833x; 1.2833x over previous
#include <cuda_runtime.h>
#include <cstdint>

#define NSTEP 2176
#define NPAIR (NSTEP / 2)
#define BURN  128
#define DIMX  512
#define HID   1024
#define GT    16            // t-tile for dz GEMM

// fixed-point scale for deterministic integer reduction
#define RSCALE  33554432.0f          // 2^25
#define RISCALE 2.9802322387695312e-8f // 2^-25

// ---------------- scratch (device globals: no allocation allowed) ----------
__device__ float g_dx[NSTEP * DIMX];   // scaled noise: normal * 0.1
__device__ float g_u [NSTEP];          // per-step uniforms
__device__ float g_dz[NSTEP * HID];    // dz[t][j] = sum_i dx[t][i] * W1[i][j]
__device__ float g_z0[HID];            // z0 = x0 @ W1 + b1

// ---------------- threefry2x32 (JAX-exact, partitionable) ------------------
__device__ __forceinline__ uint32_t rotl32(uint32_t v, int r) {
    return (v << r) | (v >> (32 - r));
}
__device__ __forceinline__ void tf2x32(uint32_t k0, uint32_t k1,
                                       uint32_t x0, uint32_t x1,
                                       uint32_t& o0, uint32_t& o1) {
    uint32_t k2 = k0 ^ k1 ^ 0x1BD11BDAu;
    x0 += k0; x1 += k1;
#define TF_R(R) { x0 += x1; x1 = rotl32(x1, R); x1 ^= x0; }
    TF_R(13) TF_R(15) TF_R(26) TF_R(6)
    x0 += k1; x1 += k2 + 1u;
    TF_R(17) TF_R(29) TF_R(16) TF_R(24)
    x0 += k2; x1 += k0 + 2u;
    TF_R(13) TF_R(15) TF_R(26) TF_R(6)
    x0 += k0; x1 += k1 + 3u;
    TF_R(17) TF_R(29) TF_R(16) TF_R(24)
    x0 += k1; x1 += k2 + 4u;
    TF_R(13) TF_R(15) TF_R(26) TF_R(6)
    x0 += k2; x1 += k0 + 5u;
#undef TF_R
    o0 = x0; o1 = x1;
}

__device__ __forceinline__ uint32_t rbits32(uint32_t k0, uint32_t k1, uint32_t idx) {
    uint32_t o0, o1;
    tf2x32(k0, k1, 0u, idx, o0, o1);
    return o0 ^ o1;
}

__device__ __forceinline__ float bits_to_unit(uint32_t b) {
    return __uint_as_float((b >> 9) | 0x3f800000u) - 1.0f;
}

// XLA ErfInv32 (Giles). log1pf == libdevice __nv_log1pf == what XLA emits.
__device__ __forceinline__ float erfinv_xla(float x) {
    float xx = x * x;
    float w = -log1pf(-xx);
    float p;
    if (w < 5.0f) {
        w = w - 2.5f;
        p = 2.81022636e-08f;
        p = fmaf(p, w, 3.43273939e-07f);
        p = fmaf(p, w, -3.5233877e-06f);
        p = fmaf(p, w, -4.39150654e-06f);
        p = fmaf(p, w, 0.00021858087f);
        p = fmaf(p, w, -0.00125372503f);
        p = fmaf(p, w, -0.00417768164f);
        p = fmaf(p, w, 0.246640727f);
        p = fmaf(p, w, 1.50140941f);
    } else {
        w = __fsqrt_rn(w) - 3.0f;
        p = -0.000200214257f;
        p = fmaf(p, w, 0.000100950558f);
        p = fmaf(p, w, 0.00134934322f);
        p = fmaf(p, w, -0.00367342844f);
        p = fmaf(p, w, 0.00573950773f);
        p = fmaf(p, w, -0.0076224613f);
        p = fmaf(p, w, 0.00943887047f);
        p = fmaf(p, w, 1.00167406f);
        p = fmaf(p, w, 2.83297682f);
    }
    return p * x;
}

// ---------------- f32x2 packed helpers (Blackwell) --------------------------
typedef unsigned long long ull;
__device__ __forceinline__ ull pk2(float a, float b) {
    ull r; asm("mov.b64 %0, {%1, %2};" : "=l"(r) : "f"(a), "f"(b)); return r;
}
__device__ __forceinline__ void upk2(float& a, float& b, ull v) {
    asm("mov.b64 {%0, %1}, %2;" : "=f"(a), "=f"(b) : "l"(v));
}
__device__ __forceinline__ ull cst2(float c) {
    uint32_t u = __float_as_uint(c);
    return ((ull)u << 32) | (ull)u;
}
#define FMA2(d, a, b, c) asm("fma.rn.f32x2 %0, %1, %2, %3;" : "=l"(d) : "l"(a), "l"(b), "l"(c))
#define MUL2(d, a, b)    asm("mul.rn.f32x2 %0, %1, %2;"     : "=l"(d) : "l"(a), "l"(b))
#define ADD2(d, a, b)    asm("add.rn.f32x2 %0, %1, %2;"     : "=l"(d) : "l"(a), "l"(b))
// d = a - b  (one FMA2: a + (-1)*b)
#define SUB2(d, a, b)    asm("fma.rn.f32x2 %0, %1, %2, %3;" : "=l"(d) : "l"(b), "l"(0xBF800000BF800000ULL), "l"(a))

__device__ __forceinline__ float rcp_approx(float x) {
    float r; asm("rcp.approx.f32 %0, %1;" : "=f"(r) : "f"(x)); return r;
}
__device__ __forceinline__ float ex2_approx(float x) {
    float r; asm("ex2.approx.f32 %0, %1;" : "=f"(r) : "f"(x)); return r;
}

// HW integer warp reduction (sm_80+), broadcasts to all lanes
__device__ __forceinline__ int redux_add_s32(int v) {
    int r; asm("redux.sync.add.s32 %0, %1, 0xffffffff;" : "=r"(r) : "r"(v));
    return r;
}

// MUFU-pipe tanh over a packed pair: tanh(x) = 1 - 2/(e^{2x}+1)
__device__ __forceinline__ void tanh2_mufu(ull X, float& ra, float& rb) {
    ull S; MUL2(S, X, cst2(2.8853900817779268f));   // 2*log2(e)*x
    float sa, sb; upk2(sa, sb, S);
    float Ea = ex2_approx(sa), Eb = ex2_approx(sb); // e^{2x}
    ull D; ADD2(D, pk2(Ea, Eb), cst2(1.0f));
    float da, db; upk2(da, db, D);
    ull R = pk2(rcp_approx(da), rcp_approx(db));
    ull T; FMA2(T, R, cst2(-2.0f), cst2(1.0f));
    upk2(ra, rb, T);
}

// ---------------- kernel 1: precompute all noise / uniforms ----------------
__global__ void __launch_bounds__(256) noise_kernel() {
    const int t = blockIdx.x;
    const int tid = threadIdx.x;

    uint32_t kt0, kt1;
    tf2x32(0u, 1u, 0u, (uint32_t)t, kt0, kt1);

    uint32_t n0, n1, u0, u1;
    tf2x32(kt0, kt1, 0u, 0u, n0, n1);   // k_noise
    tf2x32(kt0, kt1, 0u, 1u, u0, u1);   // k_unif

    const float LO = __uint_as_float(0xBF7FFFFFu);      // nextafter(-1,0)
    const float SQRT2 = __uint_as_float(0x3FB504F3u);   // f32(sqrt(2))
    const float STEP = 0.1f;

#pragma unroll
    for (int h = 0; h < 2; ++h) {
        int i = tid + h * 256;
        uint32_t b = rbits32(n0, n1, (uint32_t)i);
        float f = bits_to_unit(b);
        float u = fmaxf(LO, f * 2.0f + LO);
        float nv = SQRT2 * erfinv_xla(u);
        g_dx[t * DIMX + i] = nv * STEP;
    }

    if (tid == 0) {
        uint32_t b = rbits32(u0, u1, 0u);
        g_u[t] = bits_to_unit(b);
    }
}

// ---------------- kernel 2: dz[t][j] = dx[t] @ W1 (packed t-pairs) ---------
__global__ void __launch_bounds__(256) dz_gemm(const float* __restrict__ W1) {
    __shared__ float dxs[GT * DIMX];            // 32 KB
    const int tx = threadIdx.x;
    const int j  = blockIdx.x * 256 + tx;
    const int t0 = blockIdx.y * GT;

    for (int k = tx; k < GT * DIMX; k += 256) dxs[k] = g_dx[t0 * DIMX + k];
    __syncthreads();

    ull acc[GT / 2];
#pragma unroll
    for (int q = 0; q < GT / 2; ++q) acc[q] = 0;

#pragma unroll 4
    for (int i = 0; i < DIMX; ++i) {
        float wv = W1[i * HID + j];
        ull WV = pk2(wv, wv);
#pragma unroll
        for (int q = 0; q < GT / 2; ++q) {
            ull DX = pk2(dxs[(2 * q) * DIMX + i], dxs[(2 * q + 1) * DIMX + i]);
            FMA2(acc[q], WV, DX, acc[q]);
        }
    }
#pragma unroll
    for (int q = 0; q < GT / 2; ++q) {
        float a, b; upk2(a, b, acc[q]);
        g_dz[(t0 + 2 * q) * HID + j] = a;
        g_dz[(t0 + 2 * q + 1) * HID + j] = b;
    }
}

// ---------------- kernel 3: z0 = x0 @ W1 + b1 ------------------------------
__global__ void __launch_bounds__(256) z0_kernel(const float* __restrict__ x0,
                                                 const float* __restrict__ W1,
                                                 const float* __restrict__ b1) {
    __shared__ float xs[DIMX];
    const int tx = threadIdx.x;
    const int j  = blockIdx.x * 256 + tx;
    for (int k = tx; k < DIMX; k += 256) xs[k] = x0[k];
    __syncthreads();
    float acc = 0.0f;
    for (int i = 0; i < DIMX; ++i)
        acc = fmaf(xs[i], W1[i * HID + j], acc);
    g_z0[j] = acc + b1[j];
}

// ---------------- kernel 4: chain, ONE CTA, 512 thr, 2-step speculation ----
// Thread owns hidden cols (tid, tid+512) packed as one f32x2, and x dim tid.
// Reductions in fixed-point s32 via redux.sync (deterministic, shallow).
__global__ void __launch_bounds__(512, 1) chain_kernel(
    const float* __restrict__ x0, const float* __restrict__ W2,
    const float* __restrict__ b2, float* __restrict__ out)
{
    __shared__ int   red[2][3][16];     // [parity][chain][warp] (int partials)
    __shared__ float us[NSTEP];

    const int tid  = threadIdx.x;
    const int lane = tid & 31;
    const int wid  = tid >> 5;          // 16 warps

    for (int k = tid; k < NSTEP; k += 512) us[k] = g_u[k];

    ull zP = pk2(g_z0[tid], g_z0[tid + DIMX]);   // b1 folded in
    ull cP = 0;                                   // Kahan compensation (0.0,0.0)
    const float W2a = W2[tid], W2b = W2[tid + DIMX];
    const float b2v = b2[0];
    float xr = x0[tid];
    float p_old;

    // ---- initial p_old = psi2(x0) ----
    {
        float ta, tb; tanh2_mufu(zP, ta, tb);
        float y = fmaf(tb, W2b, ta * W2a);
        int yi = __float2int_rn(y * RSCALE);
        yi = redux_add_s32(yi);
        if (lane == 0) red[1][0][wid] = yi;
        __syncthreads();
        int v = (lane < 16) ? red[1][0][lane] : 0;
        v = redux_add_s32(v);
        float s = (float)v * RISCALE;
        float m = s + b2v;
        p_old = m * m;
        __syncthreads();
    }

    // prefetch pair 0
    ull d0 = pk2(g_dz[0 * HID + tid], g_dz[0 * HID + tid + DIMX]);
    ull d1 = pk2(g_dz[1 * HID + tid], g_dz[1 * HID + tid + DIMX]);
    float dx0 = g_dx[0 * DIMX + tid], dx1 = g_dx[1 * DIMX + tid];

    for (int m = 0; m < NPAIR; ++m) {
        const int t0 = 2 * m;
        const int par = m & 1;

        // candidates (packed bitwise replay of the sequential Kahan recurrence)
        ull e0;  SUB2(e0, d0, cP);
        ull v0;  ADD2(v0, zP, e0);          // step t0 arg / accept-z
        ull tt;  SUB2(tt, v0, zP);
        ull c0;  SUB2(c0, tt, e0);
        ull r1;  SUB2(r1, d1, cP);
        ull v1r; ADD2(v1r, zP, r1);         // t1 | reject
        ull a1p; SUB2(a1p, d1, c0);
        ull v1a; ADD2(v1a, v0, a1p);        // t1 | accept

        float t0a, t0b, t1ra, t1rb, t1aa, t1ab;
        tanh2_mufu(v0,  t0a,  t0b);
        tanh2_mufu(v1r, t1ra, t1rb);
        tanh2_mufu(v1a, t1aa, t1ab);
        float y0  = fmaf(t0b,  W2b, t0a  * W2a);
        float y1r = fmaf(t1rb, W2b, t1ra * W2a);
        float y1a = fmaf(t1ab, W2b, t1aa * W2a);

        // stage 1: HW integer warp reductions (fixed-point 2^25)
        int i0 = redux_add_s32(__float2int_rn(y0  * RSCALE));
        int i1 = redux_add_s32(__float2int_rn(y1r * RSCALE));
        int i2 = redux_add_s32(__float2int_rn(y1a * RSCALE));
        if (lane == 0) {
            red[par][0][wid] = i0;
            red[par][1][wid] = i1;
            red[par][2][wid] = i2;
        }
        __syncthreads();

        // prefetch next pair (overlaps stage 2)
        ull nd0 = 0, nd1 = 0;
        float ndx0 = 0.f, ndx1 = 0.f;
        if (m + 1 < NPAIR) {
            const int tn = 2 * m + 2;
            nd0 = pk2(g_dz[tn * HID + tid],       g_dz[tn * HID + tid + DIMX]);
            nd1 = pk2(g_dz[(tn + 1) * HID + tid], g_dz[(tn + 1) * HID + tid + DIMX]);
            ndx0 = g_dx[tn * DIMX + tid];
            ndx1 = g_dx[(tn + 1) * DIMX + tid];
        }

        // stage 2: one redux per chain over the 16 partials
        int w0 = (lane < 16) ? red[par][0][lane] : 0;
        int w1 = (lane < 16) ? red[par][1][lane] : 0;
        int w2 = (lane < 16) ? red[par][2][lane] : 0;
        w0 = redux_add_s32(w0);
        w1 = redux_add_s32(w1);
        w2 = redux_add_s32(w2);
        float s0  = (float)w0 * RISCALE;
        float s1r = (float)w1 * RISCALE;
        float s1a = (float)w2 * RISCALE;

        // decisions (uniform): u < min(p_new/(p_old+eps),1) <=> u*(p_old+eps) < p_new
        float m0 = s0 + b2v;
        float p0 = m0 * m0;
        bool a0 = us[t0] * (p_old + 1e-12f) < p0;
        float pm = a0 ? p0 : p_old;
        float s1 = a0 ? s1a : s1r;
        float m1 = s1 + b2v;
        float p1 = m1 * m1;
        bool a1 = us[t0 + 1] * (pm + 1e-12f) < p1;
        p_old = a1 ? p1 : pm;

        // apply step t0
        if (a0) { zP = v0; cP = c0; xr += dx0; }
        if (t0 >= BURN) out[(t0 - BURN) * DIMX + tid] = xr;
        // apply step t1 (packed Kahan add of d1)
        if (a1) {
            ull e;  SUB2(e, d1, cP);
            ull zn; ADD2(zn, zP, e);
            ull u;  SUB2(u, zn, zP);
            SUB2(cP, u, e);
            zP = zn;
            xr += dx1;
        }
        if (t0 + 1 >= BURN) out[(t0 + 1 - BURN) * DIMX + tid] = xr;

        d0 = nd0; d1 = nd1; dx0 = ndx0; dx1 = ndx1;
    }
}

// ---------------- launch ----------------------------------------------------
extern "C" void kernel_launch(void* const* d_in, const int* in_sizes, int n_in,
                              void* d_out, int out_size) {
    const float* x0 = (const float*)d_in[0];
    const float* W1 = (const float*)d_in[1];
    const float* b1 = (const float*)d_in[2];
    const float* W2 = (const float*)d_in[3];
    const float* b2 = (const float*)d_in[4];
    float* out = (float*)d_out;

    noise_kernel<<<NSTEP, 256>>>();
    dz_gemm<<<dim3(HID / 256, NSTEP / GT), 256>>>(W1);
    z0_kernel<<<HID / 256, 256>>>(x0, W1, b1);
    chain_kernel<<<1, 512>>>(x0, W2, b2, out);
}